// round 2
// baseline (speedup 1.0000x reference)
#include <cuda_runtime.h>
#include <cstdint>

#define DDIM 64
#define KCODES 1024
#define NTOK 131072
#define TM 128
#define NTHREADS 256
#define SMEM_BYTES (65536 + 32768 + 512 + 512 + 512)

typedef unsigned long long ull;

// Persistent scratch: transposed codebook + ||c||^2 (sequential-sum, matching XLA)
__device__ float g_cbT[DDIM * KCODES];  // [d][k]
__device__ float g_cn[KCODES];          // ||c_k||^2

__global__ void vq_prep(const float* __restrict__ cb) {
    int k = blockIdx.x * blockDim.x + threadIdx.x;
    if (k >= KCODES) return;
    float acc = 0.f;
#pragma unroll
    for (int d = 0; d < DDIM; d++) {
        float c = cb[k * DDIM + d];
        acc = __fadd_rn(acc, __fmul_rn(c, c));   // sequential, no FMA contraction
        g_cbT[d * KCODES + k] = c;
    }
    g_cn[k] = acc;
}

// One CTA: 128 tokens x all 1024 codes. 256 threads; thread tile 8 tokens x 8 codes
// as 8x4 f32x2 accumulators (lanes = adjacent code pair) computing s = x.c via
// ascending-d FMA chain from 0 (bit-matches BLAS k-sequential FMA accumulation).
// Final compare value replicates reference exactly: d2 = fl(fl(xn - 2s) + cn).
__global__ __launch_bounds__(NTHREADS, 2)
void vq_main(const float* __restrict__ h, const float* __restrict__ cb,
             float* __restrict__ outZ, float* __restrict__ outQ) {
    extern __shared__ char smem[];
    float2* Xs2 = (float2*)smem;                         // [64][128] replicated {x,x}  (64KB)
    float*  Cs  = (float*)(smem + 65536);                // [64][128]                   (32KB)
    float*  Cn  = (float*)(smem + 65536 + 32768);        // [128]  ||c||^2
    int*    wix = (int*)(smem + 65536 + 32768 + 512);    // [128]
    float*  xns = (float*)(smem + 65536 + 32768 + 1024); // [128]  ||x||^2
    float*  redv = (float*)(smem + 65536);               // overlays Cs after compute
    int*    redi = (int*)(smem + 65536 + 16 * 128 * 4);

    const int tid = threadIdx.x;
    const int tx = tid & 15;   // code group
    const int ty = tid >> 4;   // token group
    const int n0 = blockIdx.x * TM;
    const int b = n0 >> 12;
    const long base = (long)b * 262144 + (n0 & 4095);

    // Load X tile: for each d, 128 contiguous floats (tile never crosses batch: 4096%128==0)
    for (int i = tid; i < 64 * 32; i += NTHREADS) {
        int d = i >> 5;
        int t4 = i & 31;
        float4 v = *(const float4*)(h + base + (long)d * 4096 + t4 * 4);
        int t = t4 * 4;
        Xs2[d * 128 + t + 0] = make_float2(v.x, v.x);
        Xs2[d * 128 + t + 1] = make_float2(v.y, v.y);
        Xs2[d * 128 + t + 2] = make_float2(v.z, v.z);
        Xs2[d * 128 + t + 3] = make_float2(v.w, v.w);
    }
    __syncthreads();

    // xn = sum_d x_d^2, strictly sequential mul-then-add (replicates XLA reduce order)
    if (tid < 128) {
        float acc = 0.f;
#pragma unroll
        for (int d = 0; d < 64; d++) {
            float xv = Xs2[d * 128 + tid].x;
            acc = __fadd_rn(acc, __fmul_rn(xv, xv));
        }
        xns[tid] = acc;
    }

    float bv[8];
    int bi[8];
#pragma unroll
    for (int t = 0; t < 8; t++) { bv[t] = 3.4e38f; bi[t] = 0; }

    for (int kt = 0; kt < 8; kt++) {
        __syncthreads();
        // Load code tile [64][128] from transposed codebook (coalesced)
        for (int i = tid; i < 64 * 32; i += NTHREADS) {
            int d = i >> 5;
            int k4 = i & 31;
            *(float4*)&Cs[d * 128 + k4 * 4] =
                *(const float4*)&g_cbT[d * KCODES + kt * 128 + k4 * 4];
        }
        if (tid < 32)
            *(float4*)&Cn[tid * 4] = *(const float4*)&g_cn[kt * 128 + tid * 4];
        __syncthreads();

        ull acc[8][4];
#pragma unroll
        for (int t = 0; t < 8; t++)
#pragma unroll
            for (int kp = 0; kp < 4; kp++) acc[t][kp] = 0ull;  // s starts at 0 (BLAS-exact)

#pragma unroll 8
        for (int d = 0; d < 64; d++) {
            const ull* crow = (const ull*)&Cs[d * 128 + tx * 8];
            ull cp0 = crow[0], cp1 = crow[1], cp2 = crow[2], cp3 = crow[3];
            const ull* xrow = (const ull*)&Xs2[d * 128 + ty * 8];
#pragma unroll
            for (int t = 0; t < 8; t++) {
                ull x = xrow[t];  // {x,x}
                asm("fma.rn.f32x2 %0, %1, %2, %0;" : "+l"(acc[t][0]) : "l"(x), "l"(cp0));
                asm("fma.rn.f32x2 %0, %1, %2, %0;" : "+l"(acc[t][1]) : "l"(x), "l"(cp1));
                asm("fma.rn.f32x2 %0, %1, %2, %0;" : "+l"(acc[t][2]) : "l"(x), "l"(cp2));
                asm("fma.rn.f32x2 %0, %1, %2, %0;" : "+l"(acc[t][3]) : "l"(x), "l"(cp3));
            }
        }

        // Running argmin on d2 = fl(fl(xn - 2s) + cn); strict < keeps earliest index
        // (per-thread k visited ascending across kt and within the 8-code group).
        const int kbase = kt * 128 + tx * 8;
        const ull* cnp = (const ull*)&Cn[tx * 8];
#pragma unroll
        for (int t = 0; t < 8; t++) {
            float xnv = xns[ty * 8 + t];
#pragma unroll
            for (int kp = 0; kp < 4; kp++) {
                ull cn2 = cnp[kp];
                float slo = __uint_as_float((unsigned)(acc[t][kp] & 0xffffffffull));
                float shi = __uint_as_float((unsigned)(acc[t][kp] >> 32));
                float cnlo = __uint_as_float((unsigned)(cn2 & 0xffffffffull));
                float cnhi = __uint_as_float((unsigned)(cn2 >> 32));
                float dlo = __fadd_rn(__fsub_rn(xnv, 2.0f * slo), cnlo);
                float dhi = __fadd_rn(__fsub_rn(xnv, 2.0f * shi), cnhi);
                if (dlo < bv[t]) { bv[t] = dlo; bi[t] = kbase + 2 * kp; }
                if (dhi < bv[t]) { bv[t] = dhi; bi[t] = kbase + 2 * kp + 1; }
            }
        }
    }

    __syncthreads();
#pragma unroll
    for (int t = 0; t < 8; t++) {
        redv[tx * 128 + ty * 8 + t] = bv[t];
        redi[tx * 128 + ty * 8 + t] = bi[t];
    }
    __syncthreads();

    if (tid < 128) {
        float best = redv[tid];
        int besti = redi[tid];
#pragma unroll
        for (int x = 1; x < 16; x++) {
            float v = redv[x * 128 + tid];
            int i2 = redi[x * 128 + tid];
            if (v < best || (v == best && i2 < besti)) { best = v; besti = i2; }
        }
        wix[tid] = besti;
        if (outZ) outZ[n0 + tid] = (float)besti;
    }
    __syncthreads();

    if (outQ) {
        for (int i = tid; i < 128 * 16; i += NTHREADS) {
            int t = i >> 4;
            int c4 = i & 15;
            float4 v = *(const float4*)&cb[wix[t] * DDIM + c4 * 4];
            *(float4*)&outQ[(long)(n0 + t) * DDIM + c4 * 4] = v;
        }
    }
}

extern "C" void kernel_launch(void* const* d_in, const int* in_sizes, int n_in,
                              void* d_out, int out_size) {
    const float* h = (const float*)d_in[0];
    const float* cb = (const float*)d_in[1];
    float* out = (float*)d_out;

    float* outZ = nullptr;
    float* outQ = nullptr;
    if (out_size >= NTOK + NTOK * DDIM) {      // (z, q) concatenated, z first
        outZ = out;
        outQ = out + NTOK;
    } else if (out_size == NTOK * DDIM) {      // q only
        outQ = out;
    } else {                                   // z only
        outZ = out;
    }

    cudaFuncSetAttribute(vq_main, cudaFuncAttributeMaxDynamicSharedMemorySize, SMEM_BYTES);
    vq_prep<<<(KCODES + 255) / 256, 256>>>(cb);
    vq_main<<<NTOK / TM, NTHREADS, SMEM_BYTES>>>(h, cb, outZ, outQ);
}